// round 10
// baseline (speedup 1.0000x reference)
#include <cuda_runtime.h>
#include <math.h>
#include <stdint.h>

// x: (4,192,256,256) fp32, WS=8, shift=4, NHEADS=4, HD=48, nW=4096, T=64
// 512 threads (16 warps), 1 window/CTA. tf32 mma.sync m16n8k8.
// Weights staged via double-buffered cp.async; B-frags from SMEM (stride 200
// = 8 mod 32, conflict-free). Warp tile m32 x n24 (2m x 8n slabs).
// Activation buffers t-major stride 196 (=4 mod 32): conflict-free frags.
#define NT 512
#define SA 196
#define SP 68
#define SW 200
#define OFF_X 0          // LN1 out / residual  64x196 = 12544 f
#define OFF_Q 12544      // Q -> O concat
#define OFF_K 25088      // K -> H (LN2 out)
#define OFF_V 37632      // V -> G (gelu out)
#define OFF_P 50176      // scores 64x68 / LN scratch / out staging (4352 f)
#define OFF_S0 50176     // weight stage buf0 (UNION with P: disjoint in time)
#define OFF_S1 53376     // weight stage buf1
#define SMEM_FLOATS 56576
#define SMEM_BYTES (SMEM_FLOATS * 4)   // 226304 B

__device__ __forceinline__ void mma_tf32(float (&d)[4],
                                         uint32_t a0, uint32_t a1, uint32_t a2, uint32_t a3,
                                         uint32_t b0, uint32_t b1)
{
    asm volatile(
        "mma.sync.aligned.m16n8k8.row.col.f32.tf32.tf32.f32 "
        "{%0,%1,%2,%3}, {%4,%5,%6,%7}, {%8,%9}, {%0,%1,%2,%3};"
        : "+f"(d[0]), "+f"(d[1]), "+f"(d[2]), "+f"(d[3])
        : "r"(a0), "r"(a1), "r"(a2), "r"(a3), "r"(b0), "r"(b1));
}

// stage one 16-row k-tile of weights into smem ring buffer (coalesced cp.async)
__device__ __forceinline__ void stage_async(float* __restrict__ sm, int soff,
                                            const float* __restrict__ w,
                                            int wld, int col0, int k0, int tid)
{
    for (int l = tid; l < 768; l += NT) {        // 768 float4 (16 x 48)
        const int kk = l / 48, j4 = l - kk * 48;
        const uint32_t dst =
            (uint32_t)__cvta_generic_to_shared(&sm[soff + kk * SW + j4 * 4]);
        asm volatile("cp.async.ca.shared.global [%0], [%1], 16;\n"
                     :: "r"(dst), "l"(&w[(size_t)(k0 + kk) * wld + col0 + j4 * 4]));
    }
}

// acc[2][3][4] += A(64x192 smem, t-major SA) @ w[:, col0..col0+191]
// warp tile: rows mi*32..+32, cols nj*24..+24. Double-buffered cp.async.
__device__ __forceinline__ void gemm_staged(float* __restrict__ sm,
                                            const float* __restrict__ sA,
                                            const float* __restrict__ w,
                                            int wld, int col0,
                                            int tid, int lane, int mi, int nj,
                                            float (&acc)[2][3][4])
{
    const int gr = lane >> 2, tg = lane & 3;
    stage_async(sm, OFF_S0, w, wld, col0, 0, tid);
    asm volatile("cp.async.commit_group;");
    #pragma unroll 1
    for (int kt = 0; kt < 12; kt++) {
        if (kt < 11) {
            stage_async(sm, (kt & 1) ? OFF_S0 : OFF_S1, w, wld, col0, (kt + 1) * 16, tid);
            asm volatile("cp.async.commit_group;");
            asm volatile("cp.async.wait_group 1;");
        } else {
            asm volatile("cp.async.wait_group 0;");
        }
        __syncthreads();
        const float* sW = &sm[(kt & 1) ? OFF_S1 : OFF_S0];
        #pragma unroll
        for (int ks = 0; ks < 2; ks++) {
            const float* Bb = sW + (ks * 8 + tg) * SW + nj * 24 + gr;
            uint32_t b0[3], b1[3];
            #pragma unroll
            for (int sn = 0; sn < 3; sn++) {
                b0[sn] = __float_as_uint(Bb[sn * 8]);
                b1[sn] = __float_as_uint(Bb[4 * SW + sn * 8]);
            }
            #pragma unroll
            for (int s = 0; s < 2; s++) {
                const float* Ab = sA + (mi * 32 + s * 16 + gr) * SA + kt * 16 + ks * 8 + tg;
                const uint32_t a0 = __float_as_uint(Ab[0]);
                const uint32_t a1 = __float_as_uint(Ab[8 * SA]);
                const uint32_t a2 = __float_as_uint(Ab[4]);
                const uint32_t a3 = __float_as_uint(Ab[8 * SA + 4]);
                #pragma unroll
                for (int sn = 0; sn < 3; sn++)
                    mma_tf32(acc[s][sn], a0, a1, a2, a3, b0[sn], b1[sn]);
            }
        }
        __syncthreads();
    }
}

// token-parallel LayerNorm on t-major buffers (sync at entry and exit)
// 512 threads: 64 tokens x 8 chunks of 24 channels
__device__ __forceinline__ void layernorm(float* __restrict__ sm,
                                          int src, int dst,
                                          const float* __restrict__ g,
                                          const float* __restrict__ bp,
                                          int tid)
{
    __syncthreads();
    const int t = tid & 63, chk = tid >> 6;       // 8 chunks of 24 channels
    {
        const float* row = &sm[src + t * SA + chk * 24];
        float s = 0.f, s2 = 0.f;
        #pragma unroll
        for (int j4 = 0; j4 < 6; j4++) {
            const float4 v = *(const float4*)&row[j4 * 4];
            s  += v.x + v.y + v.z + v.w;
            s2 += v.x * v.x + v.y * v.y + v.z * v.z + v.w * v.w;
        }
        sm[OFF_P + chk * 64 + t]       = s;
        sm[OFF_P + 512 + chk * 64 + t] = s2;
    }
    __syncthreads();
    if (tid < 64) {
        float s = 0.f, s2 = 0.f;
        #pragma unroll
        for (int ch = 0; ch < 8; ch++) {
            s  += sm[OFF_P + ch * 64 + tid];
            s2 += sm[OFF_P + 512 + ch * 64 + tid];
        }
        const float mean = s * (1.f / 192.f);
        const float var  = s2 * (1.f / 192.f) - mean * mean;
        sm[OFF_P + 1024 + tid] = mean;
        sm[OFF_P + 1088 + tid] = rsqrtf(var + 1e-5f);
    }
    __syncthreads();
    {
        const float mean = sm[OFF_P + 1024 + t];
        const float rstd = sm[OFF_P + 1088 + t];
        const float* row = &sm[src + t * SA + chk * 24];
        float* drow = &sm[dst + t * SA + chk * 24];
        #pragma unroll
        for (int j4 = 0; j4 < 6; j4++) {
            float4 v  = *(const float4*)&row[j4 * 4];
            const float4 gg = *(const float4*)&g[chk * 24 + j4 * 4];
            const float4 bb = *(const float4*)&bp[chk * 24 + j4 * 4];
            v.x = (v.x - mean) * rstd * gg.x + bb.x;
            v.y = (v.y - mean) * rstd * gg.y + bb.y;
            v.z = (v.z - mean) * rstd * gg.z + bb.z;
            v.w = (v.w - mean) * rstd * gg.w + bb.w;
            *(float4*)&drow[j4 * 4] = v;
        }
    }
    __syncthreads();
}

__global__ __launch_bounds__(NT, 1)
void swin_block_kernel(const float* __restrict__ x,
                       const float* __restrict__ g1,  const float* __restrict__ b1,
                       const float* __restrict__ wqkv,const float* __restrict__ bqkv,
                       const float* __restrict__ wo,  const float* __restrict__ bo,
                       const float* __restrict__ g2,  const float* __restrict__ b2,
                       const float* __restrict__ wm1, const float* __restrict__ bm1,
                       const float* __restrict__ wm2, const float* __restrict__ bm2,
                       float* __restrict__ out)
{
    extern __shared__ float sm[];
    const int tid  = threadIdx.x;
    const int wid  = tid >> 5;
    const int lane = tid & 31;
    const int gr   = lane >> 2, tg = lane & 3;
    const int mi   = wid & 1;               // 2 m-tiles of 32 rows
    const int nj   = wid >> 1;              // 8 n-slabs of 24 cols
    const int wi   = blockIdx.x;
    const int b    = wi >> 10;
    const int hb   = (wi >> 5) & 31;
    const int wb   = wi & 31;

    // ---- gather window into X (t-major), shift folded, coalesced gmem float4 ----
    for (int l = tid; l < 3072; l += NT) {
        const int c    = l >> 4;
        const int r16  = l & 15;
        const int ty   = r16 >> 1, half = r16 & 1;
        const int sh   = (hb * 8 + ty + 4) & 255;
        const int sw   = (wb * 8 + half * 4 + 4) & 255;
        const float4 v = *(const float4*)&x[(((size_t)(b * 192 + c)) << 16) + (sh << 8) + sw];
        const int t0 = ty * 8 + half * 4;
        sm[OFF_X + (t0 + 0) * SA + c] = v.x;
        sm[OFF_X + (t0 + 1) * SA + c] = v.y;
        sm[OFF_X + (t0 + 2) * SA + c] = v.z;
        sm[OFF_X + (t0 + 3) * SA + c] = v.w;
    }

    // ---- LN1 in place (residual base = LN1 output) ----
    layernorm(sm, OFF_X, OFF_X, g1, b1, tid);

    // ---- q / k / v GEMMs ----
    #pragma unroll 1
    for (int p = 0; p < 3; p++) {
        float acc[2][3][4];
        #pragma unroll
        for (int s = 0; s < 2; s++)
            #pragma unroll
            for (int n = 0; n < 3; n++)
                #pragma unroll
                for (int r = 0; r < 4; r++) acc[s][n][r] = 0.f;
        gemm_staged(sm, &sm[OFF_X], wqkv, 576, p * 192, tid, lane, mi, nj, acc);
        float* dst = &sm[(p == 0) ? OFF_Q : (p == 1) ? OFF_K : OFF_V];
        #pragma unroll
        for (int s = 0; s < 2; s++) {
            const int row = mi * 32 + s * 16 + gr;
            #pragma unroll
            for (int n = 0; n < 3; n++) {
                const int col = nj * 24 + n * 8 + 2 * tg;
                const float bb0 = __ldg(&bqkv[p * 192 + col]);
                const float bb1 = __ldg(&bqkv[p * 192 + col + 1]);
                dst[row * SA + col]           = acc[s][n][0] + bb0;
                dst[row * SA + col + 1]       = acc[s][n][1] + bb1;
                dst[(row + 8) * SA + col]     = acc[s][n][2] + bb0;
                dst[(row + 8) * SA + col + 1] = acc[s][n][3] + bb1;
            }
        }
    }
    __syncthreads();

    // ---- attention per head (tf32 mma); O written into Q slab in place ----
    const float scale = 0.14433756729740643f;     // 1/sqrt(48)
    for (int h = 0; h < 4; h++) {
        // scores: S = Q_h @ K_h^T (32 tasks = exactly 2 rounds on 16 warps)
        for (int t = wid; t < 32; t += 16) {
            const int mi2 = t >> 3, ni = t & 7;
            float sc[4] = {0.f, 0.f, 0.f, 0.f};
            const float* Ab = &sm[OFF_Q + (mi2 * 16 + gr) * SA + h * 48 + tg];
            const float* Bb = &sm[OFF_K + (ni * 8 + gr) * SA + h * 48 + tg];
            #pragma unroll
            for (int k8 = 0; k8 < 6; k8++) {
                const uint32_t a0 = __float_as_uint(Ab[k8 * 8]);
                const uint32_t a1 = __float_as_uint(Ab[8 * SA + k8 * 8]);
                const uint32_t a2 = __float_as_uint(Ab[k8 * 8 + 4]);
                const uint32_t a3 = __float_as_uint(Ab[8 * SA + k8 * 8 + 4]);
                const uint32_t b0 = __float_as_uint(Bb[k8 * 8]);
                const uint32_t b1 = __float_as_uint(Bb[k8 * 8 + 4]);
                mma_tf32(sc, a0, a1, a2, a3, b0, b1);
            }
            const int row = mi2 * 16 + gr, col = ni * 8 + 2 * tg;
            sm[OFF_P + row * SP + col]           = sc[0] * scale;
            sm[OFF_P + row * SP + col + 1]       = sc[1] * scale;
            sm[OFF_P + (row + 8) * SP + col]     = sc[2] * scale;
            sm[OFF_P + (row + 8) * SP + col + 1] = sc[3] * scale;
        }
        __syncthreads();

        {                          // softmax over 64 keys (8 threads/row, all 512)
            const int t = tid >> 3, qd = tid & 7;
            float* pr = &sm[OFF_P + t * SP + qd * 8];
            float m = -1e30f;
            #pragma unroll
            for (int j = 0; j < 8; j++) m = fmaxf(m, pr[j]);
            m = fmaxf(m, __shfl_xor_sync(0xffffffffu, m, 1));
            m = fmaxf(m, __shfl_xor_sync(0xffffffffu, m, 2));
            m = fmaxf(m, __shfl_xor_sync(0xffffffffu, m, 4));
            float s = 0.f;
            #pragma unroll
            for (int j = 0; j < 8; j++) { const float e = __expf(pr[j] - m); pr[j] = e; s += e; }
            s += __shfl_xor_sync(0xffffffffu, s, 1);
            s += __shfl_xor_sync(0xffffffffu, s, 2);
            s += __shfl_xor_sync(0xffffffffu, s, 4);
            const float inv = 1.f / s;
            #pragma unroll
            for (int j = 0; j < 8; j++) pr[j] *= inv;
        }
        __syncthreads();

        // AV: O_h = P @ V_h  (24 tasks over 16 warps)
        for (int t = wid; t < 24; t += 16) {
            const int mi2 = t / 6, ci = t % 6;
            float ao[4] = {0.f, 0.f, 0.f, 0.f};
            const float* Ab = &sm[OFF_P + (mi2 * 16 + gr) * SP + tg];
            const float* Bb = &sm[OFF_V + tg * SA + h * 48 + ci * 8 + gr];
            #pragma unroll
            for (int k8 = 0; k8 < 8; k8++) {
                const uint32_t a0 = __float_as_uint(Ab[k8 * 8]);
                const uint32_t a1 = __float_as_uint(Ab[8 * SP + k8 * 8]);
                const uint32_t a2 = __float_as_uint(Ab[k8 * 8 + 4]);
                const uint32_t a3 = __float_as_uint(Ab[8 * SP + k8 * 8 + 4]);
                const uint32_t b0 = __float_as_uint(Bb[k8 * 8 * SA]);
                const uint32_t b1 = __float_as_uint(Bb[(k8 * 8 + 4) * SA]);
                mma_tf32(ao, a0, a1, a2, a3, b0, b1);
            }
            const int row = mi2 * 16 + gr, col = h * 48 + ci * 8 + 2 * tg;
            sm[OFF_Q + row * SA + col]           = ao[0];
            sm[OFF_Q + row * SA + col + 1]       = ao[1];
            sm[OFF_Q + (row + 8) * SA + col]     = ao[2];
            sm[OFF_Q + (row + 8) * SA + col + 1] = ao[3];
        }
        __syncthreads();
    }

    // ---- o-proj + residual RMW into X ----
    {
        float acc[2][3][4];
        #pragma unroll
        for (int s = 0; s < 2; s++)
            #pragma unroll
            for (int n = 0; n < 3; n++)
                #pragma unroll
                for (int r = 0; r < 4; r++) acc[s][n][r] = 0.f;
        gemm_staged(sm, &sm[OFF_Q], wo, 192, 0, tid, lane, mi, nj, acc);
        #pragma unroll
        for (int s = 0; s < 2; s++) {
            const int row = mi * 32 + s * 16 + gr;
            #pragma unroll
            for (int n = 0; n < 3; n++) {
                const int col = nj * 24 + n * 8 + 2 * tg;
                const float bb0 = __ldg(&bo[col]);
                const float bb1 = __ldg(&bo[col + 1]);
                sm[OFF_X + row * SA + col]           += acc[s][n][0] + bb0;
                sm[OFF_X + row * SA + col + 1]       += acc[s][n][1] + bb1;
                sm[OFF_X + (row + 8) * SA + col]     += acc[s][n][2] + bb0;
                sm[OFF_X + (row + 8) * SA + col + 1] += acc[s][n][3] + bb1;
            }
        }
    }

    // ---- LN2: X -> H (K slab) ----
    layernorm(sm, OFF_X, OFF_K, g2, b2, tid);

    // ---- MLP: 4 hidden slabs of 192; G reuses V slab ----
    float acc2[2][3][4];
    #pragma unroll
    for (int s = 0; s < 2; s++)
        #pragma unroll
        for (int n = 0; n < 3; n++)
            #pragma unroll
            for (int r = 0; r < 4; r++) acc2[s][n][r] = 0.f;

    #pragma unroll 1
    for (int jt = 0; jt < 4; jt++) {
        float acc1[2][3][4];
        #pragma unroll
        for (int s = 0; s < 2; s++)
            #pragma unroll
            for (int n = 0; n < 3; n++)
                #pragma unroll
                for (int r = 0; r < 4; r++) acc1[s][n][r] = 0.f;
        gemm_staged(sm, &sm[OFF_K], wm1, 768, jt * 192, tid, lane, mi, nj, acc1);
        #pragma unroll
        for (int s = 0; s < 2; s++) {
            const int row = mi * 32 + s * 16 + gr;
            #pragma unroll
            for (int n = 0; n < 3; n++) {
                const int col = nj * 24 + n * 8 + 2 * tg;
                const float bb0 = __ldg(&bm1[jt * 192 + col]);
                const float bb1 = __ldg(&bm1[jt * 192 + col + 1]);
                float v0 = acc1[s][n][0] + bb0, v1 = acc1[s][n][1] + bb1;
                float v2 = acc1[s][n][2] + bb0, v3 = acc1[s][n][3] + bb1;
                v0 = 0.5f * v0 * (1.f + erff(v0 * 0.70710678118654752f));
                v1 = 0.5f * v1 * (1.f + erff(v1 * 0.70710678118654752f));
                v2 = 0.5f * v2 * (1.f + erff(v2 * 0.70710678118654752f));
                v3 = 0.5f * v3 * (1.f + erff(v3 * 0.70710678118654752f));
                sm[OFF_V + row * SA + col]           = v0;
                sm[OFF_V + row * SA + col + 1]       = v1;
                sm[OFF_V + (row + 8) * SA + col]     = v2;
                sm[OFF_V + (row + 8) * SA + col + 1] = v3;
            }
        }
        __syncthreads();            // G complete before gemm2 reads it
        gemm_staged(sm, &sm[OFF_V], wm2 + (size_t)jt * 192 * 192, 192, 0, tid, lane, mi, nj, acc2);
    }

    // ---- residual + staged scatter (3 chunks of 64 cols via P) ----
    {
        for (int ch = 0; ch < 3; ch++) {
            #pragma unroll
            for (int s = 0; s < 2; s++) {
                const int row = mi * 32 + s * 16 + gr;
                #pragma unroll
                for (int n = 0; n < 3; n++) {
                    const int col = nj * 24 + n * 8 + 2 * tg;
                    if ((col >> 6) == ch) {
                        const int cl = col & 63;
                        const float bb0 = __ldg(&bm2[col]);
                        const float bb1 = __ldg(&bm2[col + 1]);
                        sm[OFF_P + cl * SP + row]           = acc2[s][n][0] + bb0 + sm[OFF_X + row * SA + col];
                        sm[OFF_P + (cl + 1) * SP + row]     = acc2[s][n][1] + bb1 + sm[OFF_X + row * SA + col + 1];
                        sm[OFF_P + cl * SP + row + 8]       = acc2[s][n][2] + bb0 + sm[OFF_X + (row + 8) * SA + col];
                        sm[OFF_P + (cl + 1) * SP + row + 8] = acc2[s][n][3] + bb1 + sm[OFF_X + (row + 8) * SA + col + 1];
                    }
                }
            }
            __syncthreads();
            for (int l = tid; l < 1024; l += NT) {
                const int cl  = l >> 4;
                const int r16 = l & 15;
                const int ty  = r16 >> 1, half = r16 & 1;
                const int c   = ch * 64 + cl;
                const int sh  = (hb * 8 + ty + 4) & 255;
                const int sw  = (wb * 8 + half * 4 + 4) & 255;
                const float4 v = *(const float4*)&sm[OFF_P + cl * SP + ty * 8 + half * 4];
                *(float4*)&out[(((size_t)(b * 192 + c)) << 16) + (sh << 8) + sw] = v;
            }
            __syncthreads();
        }
    }
}

extern "C" void kernel_launch(void* const* d_in, const int* in_sizes, int n_in,
                              void* d_out, int out_size)
{
    (void)in_sizes; (void)n_in; (void)out_size;
    const float* x    = (const float*)d_in[0];
    const float* g1   = (const float*)d_in[1];
    const float* b1   = (const float*)d_in[2];
    const float* wqkv = (const float*)d_in[3];
    const float* bqkv = (const float*)d_in[4];
    const float* wo   = (const float*)d_in[5];
    const float* bo   = (const float*)d_in[6];
    const float* g2   = (const float*)d_in[7];
    const float* b2   = (const float*)d_in[8];
    const float* wm1  = (const float*)d_in[9];
    const float* bm1  = (const float*)d_in[10];
    const float* wm2  = (const float*)d_in[11];
    const float* bm2  = (const float*)d_in[12];
    float* out = (float*)d_out;

    cudaFuncSetAttribute(swin_block_kernel,
                         cudaFuncAttributeMaxDynamicSharedMemorySize, SMEM_BYTES);
    swin_block_kernel<<<4096, NT, SMEM_BYTES>>>(
        x, g1, b1, wqkv, bqkv, wo, bo, g2, b2, wm1, bm1, wm2, bm2, out);
}

// round 11
// speedup vs baseline: 1.9622x; 1.9622x over previous
#include <cuda_runtime.h>
#include <math.h>
#include <stdint.h>

// x: (4,192,256,256) fp32, WS=8, shift=4, NHEADS=4, HD=48, nW=4096, T=64
// 384 threads (12 warps), 1 window/CTA. tf32 mma.sync m16n8k8.
// Weights staged via WARP-PRIVATE double-buffered cp.async rings (8k x 32col,
// stride 40 = 8 mod 32): GEMMs contain NO CTA barriers. Warp tile m32 x n32.
// Activation buffers t-major stride 196 (=4 mod 32): conflict-free frags.
#define SA 196
#define SP 68
#define OFF_X 0          // LN1 out / residual  64x196 = 12544 f
#define OFF_Q 12544      // Q -> O concat
#define OFF_K 25088      // K -> H (LN2 out)
#define OFF_V 37632      // V -> G (gelu out)
#define OFF_P 50176      // scores 64x68 / LN scratch / out staging (4352 f)
#define OFF_S 50176      // per-warp stage rings (UNION with P, disjoint in time)
                         // warp w: OFF_S + w*640, two buffers of 320 f (8 x 40)
#define SMEM_FLOATS 57856
#define SMEM_BYTES (SMEM_FLOATS * 4)   // 231424 B

__device__ __forceinline__ void mma_tf32(float (&d)[4],
                                         uint32_t a0, uint32_t a1, uint32_t a2, uint32_t a3,
                                         uint32_t b0, uint32_t b1)
{
    asm volatile(
        "mma.sync.aligned.m16n8k8.row.col.f32.tf32.tf32.f32 "
        "{%0,%1,%2,%3}, {%4,%5,%6,%7}, {%8,%9}, {%0,%1,%2,%3};"
        : "+f"(d[0]), "+f"(d[1]), "+f"(d[2]), "+f"(d[3])
        : "r"(a0), "r"(a1), "r"(a2), "r"(a3), "r"(b0), "r"(b1));
}

// stage one 8-row x 32-col weight tile into this warp's ring buffer
__device__ __forceinline__ void stage_warp(float* __restrict__ sm, int sb,
                                           const float* __restrict__ w,
                                           int wld, int c0g, int k0, int lane)
{
    #pragma unroll
    for (int it = 0; it < 2; it++) {
        const int l = lane + it * 32;            // 0..63 float4 (8 rows x 8)
        const int row = l >> 3, j4 = l & 7;
        const uint32_t dst =
            (uint32_t)__cvta_generic_to_shared(&sm[sb + row * 40 + j4 * 4]);
        asm volatile("cp.async.ca.shared.global [%0], [%1], 16;\n"
                     :: "r"(dst), "l"(&w[(size_t)(k0 + row) * wld + c0g + j4 * 4]));
    }
}

// acc[2][4][4] += A(64x192 smem) @ w[:, col0+nj*32 .. +32]; NO CTA barriers.
__device__ __forceinline__ void gemm_warp(float* __restrict__ sm,
                                          const float* __restrict__ sA,
                                          const float* __restrict__ w,
                                          int wld, int col0,
                                          int lane, int mi, int nj, int wsb,
                                          float (&acc)[2][4][4])
{
    const int gr = lane >> 2, tg = lane & 3;
    const int c0g = col0 + nj * 32;
    stage_warp(sm, wsb, w, wld, c0g, 0, lane);
    asm volatile("cp.async.commit_group;");
    #pragma unroll 2
    for (int kt = 0; kt < 24; kt++) {
        if (kt < 23) {
            stage_warp(sm, wsb + ((kt + 1) & 1) * 320, w, wld, c0g, (kt + 1) * 8, lane);
            asm volatile("cp.async.commit_group;");
            asm volatile("cp.async.wait_group 1;");
        } else {
            asm volatile("cp.async.wait_group 0;");
        }
        __syncwarp();
        const float* sW = &sm[wsb + (kt & 1) * 320];
        uint32_t b0[4], b1[4];
        #pragma unroll
        for (int sn = 0; sn < 4; sn++) {
            b0[sn] = __float_as_uint(sW[tg * 40 + gr + sn * 8]);
            b1[sn] = __float_as_uint(sW[(tg + 4) * 40 + gr + sn * 8]);
        }
        #pragma unroll
        for (int s = 0; s < 2; s++) {
            const float* Ab = sA + (mi * 32 + s * 16 + gr) * SA + kt * 8 + tg;
            const uint32_t a0 = __float_as_uint(Ab[0]);
            const uint32_t a1 = __float_as_uint(Ab[8 * SA]);
            const uint32_t a2 = __float_as_uint(Ab[4]);
            const uint32_t a3 = __float_as_uint(Ab[8 * SA + 4]);
            #pragma unroll
            for (int sn = 0; sn < 4; sn++)
                mma_tf32(acc[s][sn], a0, a1, a2, a3, b0[sn], b1[sn]);
        }
        __syncwarp();
    }
}

// token-parallel LayerNorm on t-major buffers (sync at entry and exit)
__device__ __forceinline__ void layernorm(float* __restrict__ sm,
                                          int src, int dst,
                                          const float* __restrict__ g,
                                          const float* __restrict__ bp,
                                          int tid)
{
    __syncthreads();
    const int t = tid & 63, chk = tid >> 6;       // 6 chunks of 32 channels
    {
        const float* row = &sm[src + t * SA + chk * 32];
        float s = 0.f, s2 = 0.f;
        #pragma unroll
        for (int j4 = 0; j4 < 8; j4++) {
            const float4 v = *(const float4*)&row[j4 * 4];
            s  += v.x + v.y + v.z + v.w;
            s2 += v.x * v.x + v.y * v.y + v.z * v.z + v.w * v.w;
        }
        sm[OFF_P + chk * 64 + t]       = s;
        sm[OFF_P + 384 + chk * 64 + t] = s2;
    }
    __syncthreads();
    if (tid < 64) {
        float s = 0.f, s2 = 0.f;
        #pragma unroll
        for (int ch = 0; ch < 6; ch++) {
            s  += sm[OFF_P + ch * 64 + tid];
            s2 += sm[OFF_P + 384 + ch * 64 + tid];
        }
        const float mean = s * (1.f / 192.f);
        const float var  = s2 * (1.f / 192.f) - mean * mean;
        sm[OFF_P + 768 + tid] = mean;
        sm[OFF_P + 832 + tid] = rsqrtf(var + 1e-5f);
    }
    __syncthreads();
    {
        const float mean = sm[OFF_P + 768 + t];
        const float rstd = sm[OFF_P + 832 + t];
        const float* row = &sm[src + t * SA + chk * 32];
        float* drow = &sm[dst + t * SA + chk * 32];
        #pragma unroll
        for (int j4 = 0; j4 < 8; j4++) {
            float4 v = *(const float4*)&row[j4 * 4];
            const float4 gg = *(const float4*)&g[chk * 32 + j4 * 4];
            const float4 bb = *(const float4*)&bp[chk * 32 + j4 * 4];
            v.x = (v.x - mean) * rstd * gg.x + bb.x;
            v.y = (v.y - mean) * rstd * gg.y + bb.y;
            v.z = (v.z - mean) * rstd * gg.z + bb.z;
            v.w = (v.w - mean) * rstd * gg.w + bb.w;
            *(float4*)&drow[j4 * 4] = v;
        }
    }
    __syncthreads();
}

__global__ __launch_bounds__(384, 1)
void swin_block_kernel(const float* __restrict__ x,
                       const float* __restrict__ g1,  const float* __restrict__ b1,
                       const float* __restrict__ wqkv,const float* __restrict__ bqkv,
                       const float* __restrict__ wo,  const float* __restrict__ bo,
                       const float* __restrict__ g2,  const float* __restrict__ b2,
                       const float* __restrict__ wm1, const float* __restrict__ bm1,
                       const float* __restrict__ wm2, const float* __restrict__ bm2,
                       float* __restrict__ out)
{
    extern __shared__ float sm[];
    const int tid  = threadIdx.x;
    const int wid  = tid >> 5;
    const int lane = tid & 31;
    const int gr   = lane >> 2, tg = lane & 3;
    const int mi   = wid & 1;               // 2 m-tiles of 32 rows
    const int nj   = wid >> 1;              // 6 n-tiles of 32 cols
    const int wsb  = OFF_S + wid * 640;     // this warp's stage ring
    const int wi   = blockIdx.x;
    const int b    = wi >> 10;
    const int hb   = (wi >> 5) & 31;
    const int wb   = wi & 31;

    // ---- gather window into X (t-major), shift folded, coalesced gmem float4 ----
    for (int l = tid; l < 3072; l += 384) {
        const int c    = l >> 4;
        const int r16  = l & 15;
        const int ty   = r16 >> 1, half = r16 & 1;
        const int sh   = (hb * 8 + ty + 4) & 255;
        const int sw   = (wb * 8 + half * 4 + 4) & 255;
        const float4 v = *(const float4*)&x[(((size_t)(b * 192 + c)) << 16) + (sh << 8) + sw];
        const int t0 = ty * 8 + half * 4;
        sm[OFF_X + (t0 + 0) * SA + c] = v.x;
        sm[OFF_X + (t0 + 1) * SA + c] = v.y;
        sm[OFF_X + (t0 + 2) * SA + c] = v.z;
        sm[OFF_X + (t0 + 3) * SA + c] = v.w;
    }

    // ---- LN1 in place (residual base = LN1 output) ----
    layernorm(sm, OFF_X, OFF_X, g1, b1, tid);

    // ---- q / k / v GEMMs (warp-private pipelines, no CTA barriers) ----
    #pragma unroll 1
    for (int p = 0; p < 3; p++) {
        float acc[2][4][4];
        #pragma unroll
        for (int s = 0; s < 2; s++)
            #pragma unroll
            for (int n = 0; n < 4; n++)
                #pragma unroll
                for (int r = 0; r < 4; r++) acc[s][n][r] = 0.f;
        gemm_warp(sm, &sm[OFF_X], wqkv, 576, p * 192, lane, mi, nj, wsb, acc);
        float* dst = &sm[(p == 0) ? OFF_Q : (p == 1) ? OFF_K : OFF_V];
        #pragma unroll
        for (int s = 0; s < 2; s++) {
            const int row = mi * 32 + s * 16 + gr;
            #pragma unroll
            for (int n = 0; n < 4; n++) {
                const int col = nj * 32 + n * 8 + 2 * tg;
                const float bb0 = __ldg(&bqkv[p * 192 + col]);
                const float bb1 = __ldg(&bqkv[p * 192 + col + 1]);
                dst[row * SA + col]           = acc[s][n][0] + bb0;
                dst[row * SA + col + 1]       = acc[s][n][1] + bb1;
                dst[(row + 8) * SA + col]     = acc[s][n][2] + bb0;
                dst[(row + 8) * SA + col + 1] = acc[s][n][3] + bb1;
            }
        }
    }
    __syncthreads();

    // ---- attention per head (tf32 mma); O written into Q slab in place ----
    const float scale = 0.14433756729740643f;     // 1/sqrt(48)
    for (int h = 0; h < 4; h++) {
        // scores: S = Q_h @ K_h^T  (B-frag = transposed read of t-major K)
        for (int t = wid; t < 32; t += 12) {
            const int mi2 = t >> 3, ni = t & 7;
            float sc[4] = {0.f, 0.f, 0.f, 0.f};
            const float* Ab = &sm[OFF_Q + (mi2 * 16 + gr) * SA + h * 48 + tg];
            const float* Bb = &sm[OFF_K + (ni * 8 + gr) * SA + h * 48 + tg];
            #pragma unroll
            for (int k8 = 0; k8 < 6; k8++) {
                const uint32_t a0 = __float_as_uint(Ab[k8 * 8]);
                const uint32_t a1 = __float_as_uint(Ab[8 * SA + k8 * 8]);
                const uint32_t a2 = __float_as_uint(Ab[k8 * 8 + 4]);
                const uint32_t a3 = __float_as_uint(Ab[8 * SA + k8 * 8 + 4]);
                const uint32_t b0 = __float_as_uint(Bb[k8 * 8]);
                const uint32_t b1 = __float_as_uint(Bb[k8 * 8 + 4]);
                mma_tf32(sc, a0, a1, a2, a3, b0, b1);
            }
            const int row = mi2 * 16 + gr, col = ni * 8 + 2 * tg;
            sm[OFF_P + row * SP + col]           = sc[0] * scale;
            sm[OFF_P + row * SP + col + 1]       = sc[1] * scale;
            sm[OFF_P + (row + 8) * SP + col]     = sc[2] * scale;
            sm[OFF_P + (row + 8) * SP + col + 1] = sc[3] * scale;
        }
        __syncthreads();

        if (tid < 256) {          // softmax over 64 keys (4 threads/row), fp32 exact
            const int t = tid >> 2, qd = tid & 3;
            float* pr = &sm[OFF_P + t * SP + qd * 16];
            float m = -1e30f;
            #pragma unroll
            for (int j = 0; j < 16; j++) m = fmaxf(m, pr[j]);
            m = fmaxf(m, __shfl_xor_sync(0xffffffffu, m, 1));
            m = fmaxf(m, __shfl_xor_sync(0xffffffffu, m, 2));
            float s = 0.f;
            #pragma unroll
            for (int j = 0; j < 16; j++) { const float e = __expf(pr[j] - m); pr[j] = e; s += e; }
            s += __shfl_xor_sync(0xffffffffu, s, 1);
            s += __shfl_xor_sync(0xffffffffu, s, 2);
            const float inv = 1.f / s;
            #pragma unroll
            for (int j = 0; j < 16; j++) pr[j] *= inv;
        }
        __syncthreads();

        // AV: O_h = P @ V_h  (A = P stride 68, B-frag = transposed V)
        for (int t = wid; t < 24; t += 12) {
            const int mi2 = t / 6, ci = t % 6;
            float ao[4] = {0.f, 0.f, 0.f, 0.f};
            const float* Ab = &sm[OFF_P + (mi2 * 16 + gr) * SP + tg];
            const float* Bb = &sm[OFF_V + tg * SA + h * 48 + ci * 8 + gr];
            #pragma unroll
            for (int k8 = 0; k8 < 8; k8++) {
                const uint32_t a0 = __float_as_uint(Ab[k8 * 8]);
                const uint32_t a1 = __float_as_uint(Ab[8 * SP + k8 * 8]);
                const uint32_t a2 = __float_as_uint(Ab[k8 * 8 + 4]);
                const uint32_t a3 = __float_as_uint(Ab[8 * SP + k8 * 8 + 4]);
                const uint32_t b0 = __float_as_uint(Bb[k8 * 8 * SA]);
                const uint32_t b1 = __float_as_uint(Bb[(k8 * 8 + 4) * SA]);
                mma_tf32(ao, a0, a1, a2, a3, b0, b1);
            }
            const int row = mi2 * 16 + gr, col = h * 48 + ci * 8 + 2 * tg;
            sm[OFF_Q + row * SA + col]           = ao[0];
            sm[OFF_Q + row * SA + col + 1]       = ao[1];
            sm[OFF_Q + (row + 8) * SA + col]     = ao[2];
            sm[OFF_Q + (row + 8) * SA + col + 1] = ao[3];
        }
        __syncthreads();
    }

    // ---- o-proj + residual RMW into X ----
    {
        float acc[2][4][4];
        #pragma unroll
        for (int s = 0; s < 2; s++)
            #pragma unroll
            for (int n = 0; n < 4; n++)
                #pragma unroll
                for (int r = 0; r < 4; r++) acc[s][n][r] = 0.f;
        gemm_warp(sm, &sm[OFF_Q], wo, 192, 0, lane, mi, nj, wsb, acc);
        #pragma unroll
        for (int s = 0; s < 2; s++) {
            const int row = mi * 32 + s * 16 + gr;
            #pragma unroll
            for (int n = 0; n < 4; n++) {
                const int col = nj * 32 + n * 8 + 2 * tg;
                const float bb0 = __ldg(&bo[col]);
                const float bb1 = __ldg(&bo[col + 1]);
                sm[OFF_X + row * SA + col]           += acc[s][n][0] + bb0;
                sm[OFF_X + row * SA + col + 1]       += acc[s][n][1] + bb1;
                sm[OFF_X + (row + 8) * SA + col]     += acc[s][n][2] + bb0;
                sm[OFF_X + (row + 8) * SA + col + 1] += acc[s][n][3] + bb1;
            }
        }
    }

    // ---- LN2: X -> H (K slab) ----
    layernorm(sm, OFF_X, OFF_K, g2, b2, tid);

    // ---- MLP: 4 hidden slabs of 192; G reuses V slab ----
    float acc2[2][4][4];
    #pragma unroll
    for (int s = 0; s < 2; s++)
        #pragma unroll
        for (int n = 0; n < 4; n++)
            #pragma unroll
            for (int r = 0; r < 4; r++) acc2[s][n][r] = 0.f;

    #pragma unroll 1
    for (int jt = 0; jt < 4; jt++) {
        float acc1[2][4][4];
        #pragma unroll
        for (int s = 0; s < 2; s++)
            #pragma unroll
            for (int n = 0; n < 4; n++)
                #pragma unroll
                for (int r = 0; r < 4; r++) acc1[s][n][r] = 0.f;
        gemm_warp(sm, &sm[OFF_K], wm1, 768, jt * 192, lane, mi, nj, wsb, acc1);
        #pragma unroll
        for (int s = 0; s < 2; s++) {
            const int row = mi * 32 + s * 16 + gr;
            #pragma unroll
            for (int n = 0; n < 4; n++) {
                const int col = nj * 32 + n * 8 + 2 * tg;
                const float bb0 = __ldg(&bm1[jt * 192 + col]);
                const float bb1 = __ldg(&bm1[jt * 192 + col + 1]);
                float v0 = acc1[s][n][0] + bb0, v1 = acc1[s][n][1] + bb1;
                float v2 = acc1[s][n][2] + bb0, v3 = acc1[s][n][3] + bb1;
                v0 = 0.5f * v0 * (1.f + erff(v0 * 0.70710678118654752f));
                v1 = 0.5f * v1 * (1.f + erff(v1 * 0.70710678118654752f));
                v2 = 0.5f * v2 * (1.f + erff(v2 * 0.70710678118654752f));
                v3 = 0.5f * v3 * (1.f + erff(v3 * 0.70710678118654752f));
                sm[OFF_V + row * SA + col]           = v0;
                sm[OFF_V + row * SA + col + 1]       = v1;
                sm[OFF_V + (row + 8) * SA + col]     = v2;
                sm[OFF_V + (row + 8) * SA + col + 1] = v3;
            }
        }
        __syncthreads();            // G complete before gemm2 reads it
        gemm_warp(sm, &sm[OFF_V], wm2 + (size_t)jt * 192 * 192, 192, 0, lane, mi, nj, wsb, acc2);
        __syncthreads();            // G consumed before next jt overwrites
    }

    // ---- residual + staged scatter (3 chunks of 64 cols via P) ----
    {
        for (int ch = 0; ch < 3; ch++) {
            #pragma unroll
            for (int s = 0; s < 2; s++) {
                const int row = mi * 32 + s * 16 + gr;
                #pragma unroll
                for (int n = 0; n < 4; n++) {
                    const int col = nj * 32 + n * 8 + 2 * tg;
                    if ((col >> 6) == ch) {
                        const int cl = col & 63;
                        const float bb0 = __ldg(&bm2[col]);
                        const float bb1 = __ldg(&bm2[col + 1]);
                        sm[OFF_P + cl * SP + row]           = acc2[s][n][0] + bb0 + sm[OFF_X + row * SA + col];
                        sm[OFF_P + (cl + 1) * SP + row]     = acc2[s][n][1] + bb1 + sm[OFF_X + row * SA + col + 1];
                        sm[OFF_P + cl * SP + row + 8]       = acc2[s][n][2] + bb0 + sm[OFF_X + (row + 8) * SA + col];
                        sm[OFF_P + (cl + 1) * SP + row + 8] = acc2[s][n][3] + bb1 + sm[OFF_X + (row + 8) * SA + col + 1];
                    }
                }
            }
            __syncthreads();
            for (int l = tid; l < 1024; l += 384) {
                const int cl  = l >> 4;
                const int r16 = l & 15;
                const int ty  = r16 >> 1, half = r16 & 1;
                const int c   = ch * 64 + cl;
                const int sh  = (hb * 8 + ty + 4) & 255;
                const int sw  = (wb * 8 + half * 4 + 4) & 255;
                const float4 v = *(const float4*)&sm[OFF_P + cl * SP + ty * 8 + half * 4];
                *(float4*)&out[(((size_t)(b * 192 + c)) << 16) + (sh << 8) + sw] = v;
            }
            __syncthreads();
        }
    }
}

extern "C" void kernel_launch(void* const* d_in, const int* in_sizes, int n_in,
                              void* d_out, int out_size)
{
    (void)in_sizes; (void)n_in; (void)out_size;
    const float* x    = (const float*)d_in[0];
    const float* g1   = (const float*)d_in[1];
    const float* b1   = (const float*)d_in[2];
    const float* wqkv = (const float*)d_in[3];
    const float* bqkv = (const float*)d_in[4];
    const float* wo   = (const float*)d_in[5];
    const float* bo   = (const float*)d_in[6];
    const float* g2   = (const float*)d_in[7];
    const float* b2   = (const float*)d_in[8];
    const float* wm1  = (const float*)d_in[9];
    const float* bm1  = (const float*)d_in[10];
    const float* wm2  = (const float*)d_in[11];
    const float* bm2  = (const float*)d_in[12];
    float* out = (float*)d_out;

    cudaFuncSetAttribute(swin_block_kernel,
                         cudaFuncAttributeMaxDynamicSharedMemorySize, SMEM_BYTES);
    swin_block_kernel<<<4096, 384, SMEM_BYTES>>>(
        x, g1, b1, wqkv, bqkv, wo, bo, g2, b2, wm1, bm1, wm2, bm2, out);
}